// round 15
// baseline (speedup 1.0000x reference)
#include <cuda_runtime.h>
#include <cstdint>

#define BATCH 131072
#define NL    24
#define NTHR  256                      // 64 batches per block, 4 threads/batch
#define NBLK  ((BATCH * 4) / NTHR)     // 2048

__global__ __launch_bounds__(NTHR, 6)
void fk_kernel(const float* __restrict__ q,
               const float* __restrict__ axes,
               const float* __restrict__ t_fix,
               float* __restrict__ out) {
    // Packed per-link constants: cpk[l][0] = {ax,ay,az,tf0}, cpk[l][1] = {tf1,tf2,0,0}
    __shared__ float4 cpk[NL][2];

    int tid = threadIdx.x;
    if (tid < NL) {
        float ax = axes[tid * 3 + 0];
        float ay = axes[tid * 3 + 1];
        float az = axes[tid * 3 + 2];
        float inv = rsqrtf(ax * ax + ay * ay + az * az);
        cpk[tid][0] = make_float4(ax * inv, ay * inv, az * inv, t_fix[tid * 3 + 0]);
        cpk[tid][1] = make_float4(t_fix[tid * 3 + 1], t_fix[tid * 3 + 2], 0.f, 0.f);
    }
    __syncthreads();

    int gtid  = blockIdx.x * NTHR + tid;
    int batch = gtid >> 2;             // 4 consecutive lanes share a batch
    int row   = gtid & 3;              // output row this thread owns

    const float4* qr = reinterpret_cast<const float4*>(q + (size_t)batch * NL);

    // This thread's row of the running pose. Row 3 starts (0,0,0,1); the
    // uniform update keeps it constant. No divergence anywhere.
    float Ra = (row == 0) ? 1.f : 0.f;
    float Rb = (row == 1) ? 1.f : 0.f;
    float Rc = (row == 2) ? 1.f : 0.f;
    float T  = (row == 3) ? 1.f : 0.f;

    float4* gout = reinterpret_cast<float4*>(out) + (size_t)batch * (NL * 4) + row;

    float4 qnext = qr[0];

    #pragma unroll
    for (int g = 0; g < NL / 4; g++) {
        float4 qc = qnext;
        if (g < NL / 4 - 1) qnext = qr[g + 1];
        float qv[4] = {qc.x, qc.y, qc.z, qc.w};

        #pragma unroll
        for (int ll = 0; ll < 4; ll++) {
            int l = g * 4 + ll;
            float s, c;
            __sincosf(qv[ll], &s, &c);
            float C = 1.f - c;

            float4 k0 = cpk[l][0];     // ax, ay, az, tf0
            float4 k1 = cpk[l][1];     // tf1, tf2, -, -
            float ax = k0.x, ay = k0.y, az = k0.z;

            // Rodrigues: Rj = c*I + s*K + (1-c)*(a a^T)
            float j00 = fmaf(C * ax, ax, c);
            float j01 = fmaf(C * ax, ay, -s * az);
            float j02 = fmaf(C * ax, az,  s * ay);
            float j10 = fmaf(C * ay, ax,  s * az);
            float j11 = fmaf(C * ay, ay, c);
            float j12 = fmaf(C * ay, az, -s * ax);
            float j20 = fmaf(C * az, ax, -s * ay);
            float j21 = fmaf(C * az, ay,  s * ax);
            float j22 = fmaf(C * az, az, c);

            // t[row] += R[row,:] . tf   (parent R)
            T = fmaf(Ra, k0.w, fmaf(Rb, k1.x, fmaf(Rc, k1.y, T)));

            // R[row,:] = R[row,:] @ Rj
            float na = fmaf(Ra, j00, fmaf(Rb, j10, Rc * j20));
            float nb = fmaf(Ra, j01, fmaf(Rb, j11, Rc * j21));
            float nc = fmaf(Ra, j02, fmaf(Rb, j12, Rc * j22));
            Ra = na; Rb = nb; Rc = nc;

            // Direct store: lanes 4k..4k+3 write 64 B contiguous.
            __stcs(&gout[l * 4], make_float4(Ra, Rb, Rc, T));
        }
    }
}

extern "C" void kernel_launch(void* const* d_in, const int* in_sizes, int n_in,
                              void* d_out, int out_size) {
    const float* q     = (const float*)d_in[0];
    // d_in[1] = qd, unused by the reference computation
    const float* axes  = (const float*)d_in[2];
    const float* t_fix = (const float*)d_in[3];
    float* out = (float*)d_out;

    dim3 block(NTHR);
    dim3 grid(NBLK);
    fk_kernel<<<grid, block>>>(q, axes, t_fix, out);
}